// round 8
// baseline (speedup 1.0000x reference)
#include <cuda_runtime.h>
#include <cstdint>

#define T_LEN 512
#define B_SZ  2048
#define BP    (B_SZ / 2)          // 1024 batch pairs
#define HID   23
#define G3    69                  // 3*H
#define FIN   32
#define D2    46                  // 2*H
#define OUTD  8
#define M_PAIRS ((size_t)T_LEN * BP)   // 524288 row-pairs

// ---------------- scratch (device globals; no allocation) ----------------
// All intermediates are batch-PAIR interleaved: .x = batch 2p, .y = batch 2p+1
__device__ float2 g_xn2[M_PAIRS * FIN];        // [t][bp][32]
__device__ float2 g_xg2[2 * M_PAIRS * G3];     // [dir][t*BP+bp][69]
__device__ float2 g_sA2[M_PAIRS * D2];         // [t][bp][46]
__device__ float2 g_sB2[M_PAIRS * D2];         // [t][bp][46]

__device__ __forceinline__ float2 ffma2(float2 a, float2 b, float2 c) {
    union U { float2 f; unsigned long long u; };
    U ua, ub, uc, ud;
    ua.f = a; ub.f = b; uc.f = c;
    asm("fma.rn.f32x2 %0, %1, %2, %3;"
        : "=l"(ud.u) : "l"(ua.u), "l"(ub.u), "l"(uc.u));
    return ud.f;
}

__device__ __forceinline__ float sigf(float x) {
    return __fdividef(1.0f, 1.0f + __expf(-x));
}
__device__ __forceinline__ float tanh_fast(float x) {
    float a = __expf(-2.0f * fabsf(x));
    float t = __fdividef(1.0f - a, 1.0f + a);
    return copysignf(t, x);
}

// ---------------- 1) normalize + transpose [B,T,F] -> pair-interleaved [T,BP,F] ----------------
__global__ void norm_kernel(const float* __restrict__ x,
                            const float* __restrict__ fmean,
                            const float* __restrict__ fstd) {
    size_t idx = (size_t)blockIdx.x * blockDim.x + threadIdx.x;
    size_t total = M_PAIRS * FIN;
    if (idx >= total) return;
    int i = (int)(idx % FIN);
    size_t rp = idx / FIN;
    int bp = (int)(rp % BP);
    int t  = (int)(rp / BP);
    float s = fstd[i];
    s = (s == 0.0f) ? 1.0f : s;
    float2 v;
    if (s == 1.0f) {
        v.x = 0.0f; v.y = 0.0f;
    } else {
        float inv = __fdividef(1.0f, s);
        float m = fmean[i];
        int b0 = 2 * bp;
        v.x = (x[((size_t)b0 * T_LEN + t) * FIN + i] - m) * inv;
        v.y = (x[((size_t)(b0 + 1) * T_LEN + t) * FIN + i] - m) * inv;
    }
    g_xn2[idx] = v;
}

// ---------------- 2) input-gate GEMM (f32x2) ------------------------------------------------
// Block: 192 threads = 6 warps. Warp w owns 12 output cols [w*12, w*12+12).
// Block covers 64 row-pairs; lane owns pairs {lane, lane+32}.
// Weights in smem as splat float4 (2 cols per quad) -> broadcast LDS.128.
// x in smem k-major xs[k][67] -> contiguous LDS.64 per warp.
// Output staged in smem, then one contiguous float4 copy to global.
#define XS_PAD 67

template <int K>
__global__ __launch_bounds__(192, 3)
void xg_kernel(int insel, const float* __restrict__ w_ih, const float* __restrict__ b_ih) {
    const float2* in2 = (insel == 0) ? g_xn2 : ((insel == 1) ? g_sA2 : g_sB2);
    const int d = blockIdx.y;
    const float* W = w_ih + (size_t)d * G3 * K;

    extern __shared__ float sdyn[];
    float4* wq = (float4*)sdyn;                     // [K][36]  splat pairs
    float2* xs = (float2*)(wq + K * 36);            // [K][XS_PAD]

    const int tid  = threadIdx.x;
    const int w    = tid >> 5;
    const int lane = tid & 31;
    const int cbase = w * 12;
    const size_t pbase = (size_t)blockIdx.x * 64;

    // fill weights (splat-duplicated float4 covering 2 cols)
    for (int idx = tid; idx < K * 36; idx += 192) {
        int k = idx / 36, t = idx % 36;
        int g0 = 2 * t, g1 = 2 * t + 1;
        float w0 = (g0 < G3) ? W[g0 * K + k] : 0.0f;
        float w1 = (g1 < G3) ? W[g1 * K + k] : 0.0f;
        wq[idx] = make_float4(w0, w0, w1, w1);
    }
    // fill x, transposed to k-major
    for (int idx = tid; idx < 64 * K; idx += 192) {
        int p = idx / K, k = idx % K;
        xs[k * XS_PAD + p] = in2[(pbase + p) * K + k];
    }

    // init accumulators with bias
    float2 acc0[12], acc1[12];
#pragma unroll
    for (int j = 0; j < 12; j++) {
        int c = cbase + j;
        float b = (c < G3) ? b_ih[d * G3 + c] : 0.0f;
        acc0[j] = make_float2(b, b);
        acc1[j] = make_float2(b, b);
    }
    __syncthreads();

    const int wslot = w * 6;
#pragma unroll
    for (int k = 0; k < K; k++) {
        float2 xa = xs[k * XS_PAD + lane];
        float2 xb = xs[k * XS_PAD + 32 + lane];
        const float4* wrow = wq + k * 36 + wslot;
#pragma unroll
        for (int t = 0; t < 6; t++) {
            float4 q = wrow[t];
            float2 w0 = make_float2(q.x, q.y);
            float2 w1 = make_float2(q.z, q.w);
            acc0[2 * t]     = ffma2(xa, w0, acc0[2 * t]);
            acc0[2 * t + 1] = ffma2(xa, w1, acc0[2 * t + 1]);
            acc1[2 * t]     = ffma2(xb, w0, acc1[2 * t]);
            acc1[2 * t + 1] = ffma2(xb, w1, acc1[2 * t + 1]);
        }
    }

    // stage results in smem (reuse the tile space), then contiguous copy-out
    __syncthreads();
    float2* st = (float2*)sdyn;          // [64][69]
#pragma unroll
    for (int j = 0; j < 12; j++) {
        int c = cbase + j;
        if (c < G3) {
            st[(size_t)lane * G3 + c] = acc0[j];
            st[(size_t)(32 + lane) * G3 + c] = acc1[j];
        }
    }
    __syncthreads();

    float4* dst = (float4*)(g_xg2 + (size_t)d * M_PAIRS * G3 + pbase * G3);
    const float4* src = (const float4*)st;
    const int n4 = 64 * G3 / 2;   // 2208
    for (int i = tid; i < n4; i += 192) dst[i] = src[i];
}

// ---------------- 3) GRU recurrence (f32x2): one warp per (batch pair, dir) ----------------
__global__ __launch_bounds__(64)
void gru_kernel(const float* __restrict__ w_hh, const float* __restrict__ b_hh, int outsel) {
    const int d = blockIdx.y;
    const int warp = threadIdx.x >> 5;
    const int lane = threadIdx.x & 31;
    const int bp = blockIdx.x * 2 + warp;
    float2* seq2 = (outsel == 1) ? g_sA2 : g_sB2;

    __shared__ float2 hs[2][HID];

    const float* W  = w_hh + (size_t)d * G3 * HID;
    const float* bh = b_hh + d * G3;

    const int j = lane;
    const bool active = (j < HID);
    const int jj = active ? j : 0;

    float2 wr2[HID], wz2[HID], wn2[HID];
#pragma unroll
    for (int k = 0; k < HID; k++) {
        float wr = W[(jj) * HID + k];
        float wz = W[(jj + HID) * HID + k];
        float wn = W[(jj + 2 * HID) * HID + k];
        wr2[k] = make_float2(wr, wr);
        wz2[k] = make_float2(wz, wz);
        wn2[k] = make_float2(wn, wn);
    }
    float brv = bh[jj], bzv = bh[jj + HID], bnv = bh[jj + 2 * HID];
    float2 br2 = make_float2(brv, brv);
    float2 bz2 = make_float2(bzv, bzv);
    float2 bn2 = make_float2(bnv, bnv);

    if (active) hs[warp][j] = make_float2(0.0f, 0.0f);
    float2 h = make_float2(0.0f, 0.0f);
    __syncwarp();

    const float2* xgd = g_xg2 + (size_t)d * M_PAIRS * G3;
    const int t0 = (d == 0) ? 0 : (T_LEN - 1);
    const int dt = (d == 0) ? 1 : -1;

    float2 xr_n, xz_n, xn_n;
    {
        size_t row0 = ((size_t)t0 * BP + bp) * G3;
        xr_n = xgd[row0 + jj];
        xz_n = xgd[row0 + jj + HID];
        xn_n = xgd[row0 + jj + 2 * HID];
    }

    for (int s = 0; s < T_LEN; s++) {
        const int t = t0 + s * dt;
        float2 xr = xr_n, xz = xz_n, xn = xn_n;
        if (s + 1 < T_LEN) {
            size_t rown = ((size_t)(t + dt) * BP + bp) * G3;
            xr_n = xgd[rown + jj];
            xz_n = xgd[rown + jj + HID];
            xn_n = xgd[rown + jj + 2 * HID];
        }
        float2 ar = br2, az = bz2, an = bn2;
#pragma unroll
        for (int k = 0; k < HID; k++) {
            float2 hk = hs[warp][k];
            ar = ffma2(hk, wr2[k], ar);
            az = ffma2(hk, wz2[k], az);
            an = ffma2(hk, wn2[k], an);
        }
        float rX = sigf(xr.x + ar.x);
        float rY = sigf(xr.y + ar.y);
        float zX = sigf(xz.x + az.x);
        float zY = sigf(xz.y + az.y);
        float nX = tanh_fast(xn.x + rX * an.x);
        float nY = tanh_fast(xn.y + rY * an.y);
        h.x = (1.0f - zX) * nX + zX * h.x;
        h.y = (1.0f - zY) * nY + zY * h.y;

        __syncwarp();
        if (active) hs[warp][j] = h;
        __syncwarp();
        if (active) seq2[((size_t)t * BP + bp) * D2 + d * HID + j] = h;
    }
}

// ---------------- 4) FC epilogue on last timestep ----------------
__global__ void fc_kernel(const float* __restrict__ fc_w, const float* __restrict__ fc_b,
                          const float* __restrict__ omean, const float* __restrict__ ostd,
                          float* __restrict__ out) {
    int idx = blockIdx.x * blockDim.x + threadIdx.x;
    if (idx >= B_SZ * OUTD) return;
    int b = idx / OUTD, o = idx % OUTD;
    const float* lastp = (const float*)(g_sA2 + ((size_t)(T_LEN - 1) * BP + (b >> 1)) * D2);
    int par = b & 1;
    float acc = fc_b[o];
#pragma unroll
    for (int k = 0; k < D2; k++) acc += lastp[k * 2 + par] * fc_w[o * D2 + k];
    out[idx] = acc * ostd[o] + omean[o];
}

// ---------------- launch ----------------
static inline int xg_smem_bytes(int K) {
    int tile = K * 36 * 16 + K * XS_PAD * 8;     // wq + xs
    int st   = 64 * G3 * 8;                      // staging
    return (tile > st) ? tile : st;
}

extern "C" void kernel_launch(void* const* d_in, const int* in_sizes, int n_in,
                              void* d_out, int out_size) {
    const float* x         = (const float*)d_in[0];
    const float* fmean     = (const float*)d_in[1];
    const float* fstd      = (const float*)d_in[2];
    const float* omean     = (const float*)d_in[3];
    const float* ostd      = (const float*)d_in[4];
    const float* w_ih_l0   = (const float*)d_in[5];
    const float* w_hh_l0   = (const float*)d_in[6];
    const float* b_ih_l0   = (const float*)d_in[7];
    const float* b_hh_l0   = (const float*)d_in[8];
    const float* w_ih_rest = (const float*)d_in[9];
    const float* w_hh_rest = (const float*)d_in[10];
    const float* b_ih_rest = (const float*)d_in[11];
    const float* b_hh_rest = (const float*)d_in[12];
    const float* fc_w      = (const float*)d_in[13];
    const float* fc_b      = (const float*)d_in[14];
    float* out             = (float*)d_out;

    const int smem32 = xg_smem_bytes(FIN);
    const int smem46 = xg_smem_bytes(D2);
    cudaFuncSetAttribute(xg_kernel<FIN>, cudaFuncAttributeMaxDynamicSharedMemorySize, smem32);
    cudaFuncSetAttribute(xg_kernel<D2>,  cudaFuncAttributeMaxDynamicSharedMemorySize, smem46);

    // 1) normalize + pair transpose
    {
        size_t total = M_PAIRS * FIN;
        int threads = 256;
        int blocks = (int)((total + threads - 1) / threads);
        norm_kernel<<<blocks, threads>>>(x, fmean, fstd);
    }

    dim3 xg_grid((unsigned)(M_PAIRS / 64), 2);
    dim3 gru_grid(BP / 2, 2);

    // layer 0: xn2 -> sA2
    xg_kernel<FIN><<<xg_grid, 192, smem32>>>(0, w_ih_l0, b_ih_l0);
    gru_kernel<<<gru_grid, 64>>>(w_hh_l0, b_hh_l0, /*outsel=*/1);

    // layer 1: sA2 -> sB2
    xg_kernel<D2><<<xg_grid, 192, smem46>>>(1, w_ih_rest, b_ih_rest);
    gru_kernel<<<gru_grid, 64>>>(w_hh_rest, b_hh_rest, /*outsel=*/2);

    // layer 2: sB2 -> sA2
    xg_kernel<D2><<<xg_grid, 192, smem46>>>(2, w_ih_rest + (size_t)2 * G3 * D2,
                                            b_ih_rest + 2 * G3);
    gru_kernel<<<gru_grid, 64>>>(w_hh_rest + (size_t)2 * G3 * HID,
                                 b_hh_rest + 2 * G3, /*outsel=*/1);

    // FC epilogue
    {
        int threads = 256;
        int blocks = (B_SZ * OUTD + threads - 1) / threads;
        fc_kernel<<<blocks, threads>>>(fc_w, fc_b, omean, ostd, out);
    }
}

// round 9
// speedup vs baseline: 1.1026x; 1.1026x over previous
#include <cuda_runtime.h>
#include <cstdint>

#define T_LEN 512
#define B_SZ  2048
#define BP    1024                 // batch pairs
#define HID   23
#define G3    69                   // 3*H
#define FIN   32
#define D2    46                   // 2*H
#define OUTD  8
#define M_PAIRS ((size_t)T_LEN * BP)   // 524288 row-pairs

// ---------------- scratch (device globals; no allocation) ----------------
// pair-interleaved: .x = batch 2p, .y = batch 2p+1
__device__ float2 g_xg2[2 * M_PAIRS * G3];     // [dir][t*BP+bp][69]
__device__ float2 g_sA2[M_PAIRS * D2];         // [t][bp][46]
__device__ float2 g_sB2[M_PAIRS * D2];

__device__ __forceinline__ float2 ffma2(float2 a, float2 b, float2 c) {
    union U { float2 f; unsigned long long u; };
    U ua, ub, uc, ud;
    ua.f = a; ub.f = b; uc.f = c;
    asm("fma.rn.f32x2 %0, %1, %2, %3;"
        : "=l"(ud.u) : "l"(ua.u), "l"(ub.u), "l"(uc.u));
    return ud.f;
}

__device__ __forceinline__ float tanhx(float x) {
    float y;
    asm("tanh.approx.f32 %0, %1;" : "=f"(y) : "f"(x));
    return y;
}

// ---------------- input-gate GEMM (f32x2) ---------------------------------
// Block: 192 thr = 6 warps. Warp w owns cols [12w,12w+12). 64 row-pairs/block;
// lane owns pairs {2*lane, 2*lane+1} -> one aligned LDS.128 per k.
// Weights: splat float4 (2 cols) -> broadcast LDS.128.
// insel==0 reads raw x with fused normalization (no norm kernel).
#define XS_PAD 66   // even -> float4-aligned x rows

template <int K>
__global__ __launch_bounds__(192, 3)
void xg_kernel(int insel, const float* __restrict__ w_ih, const float* __restrict__ b_ih,
               const float* __restrict__ xin, const float* __restrict__ fmean,
               const float* __restrict__ fstd) {
    const int d = blockIdx.y;
    const float* W = w_ih + (size_t)d * G3 * K;

    extern __shared__ float sdyn[];
    float4* wq = (float4*)sdyn;                 // [K][36]
    float2* xs = (float2*)(wq + K * 36);        // [K][XS_PAD]

    const int tid  = threadIdx.x;
    const int w    = tid >> 5;
    const int lane = tid & 31;
    const size_t pbase = (size_t)blockIdx.x * 64;

    // weights -> smem (splat pairs)
    for (int idx = tid; idx < K * 36; idx += 192) {
        int k = idx / 36, t = idx % 36;
        int g0 = 2 * t, g1 = g0 + 1;
        float w0 = (g0 < G3) ? W[g0 * K + k] : 0.0f;
        float w1 = (g1 < G3) ? W[g1 * K + k] : 0.0f;
        wq[idx] = make_float4(w0, w0, w1, w1);
    }

    if (insel == 0) {
        // layer 0: raw x [B][T][FIN], fused normalization, transpose to k-major pairs
        __shared__ float fm_s[FIN], fi_s[FIN];
        if (tid < FIN) {
            float s = fstd[tid];
            float adj = (s == 0.0f) ? 1.0f : s;
            bool zero = (adj == 1.0f);
            fi_s[tid] = zero ? 0.0f : __fdividef(1.0f, adj);
            fm_s[tid] = zero ? 0.0f : fmean[tid];
        }
        __syncthreads();
        int t   = blockIdx.x >> 4;          // BP/64 = 16 blocks per timestep
        int bp0 = (blockIdx.x & 15) * 64;
        int b0  = 2 * bp0;
        for (int idx = tid; idx < 1024; idx += 192) {
            int row = idx >> 3;             // 0..127 (batch within tile)
            int q   = idx & 7;              // float4 within 32-feature row
            float4 v4 = *(const float4*)(xin + ((size_t)(b0 + row) * T_LEN + t) * FIN + q * 4);
            int p = row >> 1, comp = row & 1;
            int k0 = q * 4;
            const float* vv = &v4.x;
#pragma unroll
            for (int c = 0; c < 4; c++) {
                float val = (vv[c] - fm_s[k0 + c]) * fi_s[k0 + c];
                ((float*)&xs[(k0 + c) * XS_PAD + p])[comp] = val;
            }
        }
    } else {
        const float2* in2 = (insel == 1) ? g_sA2 : g_sB2;
        for (int idx = tid; idx < 64 * K; idx += 192) {
            int p = idx / K, k = idx % K;
            xs[k * XS_PAD + p] = in2[(pbase + p) * K + k];
        }
    }

    // accumulators init with bias
    float2 acc0[12], acc1[12];
#pragma unroll
    for (int j = 0; j < 12; j++) {
        int c = w * 12 + j;
        float b = (c < G3) ? b_ih[d * G3 + c] : 0.0f;
        acc0[j] = make_float2(b, b);
        acc1[j] = make_float2(b, b);
    }
    __syncthreads();

#pragma unroll
    for (int k = 0; k < K; k++) {
        float4 xv = *(const float4*)&xs[k * XS_PAD + 2 * lane];   // pairs 2l, 2l+1
        float2 xa = make_float2(xv.x, xv.y);
        float2 xb = make_float2(xv.z, xv.w);
        const float4* wr = wq + k * 36 + w * 6;
#pragma unroll
        for (int t6 = 0; t6 < 6; t6++) {
            float4 q = wr[t6];
            float2 w0 = make_float2(q.x, q.y);
            float2 w1 = make_float2(q.z, q.w);
            acc0[2 * t6]     = ffma2(xa, w0, acc0[2 * t6]);
            acc0[2 * t6 + 1] = ffma2(xa, w1, acc0[2 * t6 + 1]);
            acc1[2 * t6]     = ffma2(xb, w0, acc1[2 * t6]);
            acc1[2 * t6 + 1] = ffma2(xb, w1, acc1[2 * t6 + 1]);
        }
    }

    // stage + contiguous copy-out
    __syncthreads();
    float2* st = (float2*)sdyn;   // [64][69]
#pragma unroll
    for (int j = 0; j < 12; j++) {
        int c = w * 12 + j;
        if (c < G3) {
            st[(size_t)(2 * lane) * G3 + c]     = acc0[j];
            st[(size_t)(2 * lane + 1) * G3 + c] = acc1[j];
        }
    }
    __syncthreads();

    float4* dst = (float4*)(g_xg2 + (size_t)d * M_PAIRS * G3 + pbase * G3);
    const float4* src = (const float4*)st;
    const int n4 = 64 * G3 / 2;   // 2208
    for (int i = tid; i < n4; i += 192) dst[i] = src[i];
}

// ---------------- GRU recurrence (f32x2): one warp per (batch pair, dir) ----------------
__global__ __launch_bounds__(64)
void gru_kernel(const float* __restrict__ w_hh, const float* __restrict__ b_hh, int outsel) {
    const int d = blockIdx.y;
    const int warp = threadIdx.x >> 5;
    const int lane = threadIdx.x & 31;
    const int bp = blockIdx.x * 2 + warp;
    float2* seq2 = (outsel == 1) ? g_sA2 : g_sB2;

    __shared__ float2 hs[2][2][HID + 1];   // [warp][parity][unit]

    const float* W  = w_hh + (size_t)d * G3 * HID;
    const float* bh = b_hh + d * G3;

    const int j = lane;
    const bool active = (j < HID);
    const int jj = active ? j : 0;

    float2 wr2[HID], wz2[HID], wn2[HID];
#pragma unroll
    for (int k = 0; k < HID; k++) {
        float wr = W[(jj) * HID + k];
        float wz = W[(jj + HID) * HID + k];
        float wn = W[(jj + 2 * HID) * HID + k];
        wr2[k] = make_float2(wr, wr);
        wz2[k] = make_float2(wz, wz);
        wn2[k] = make_float2(wn, wn);
    }
    float brv = bh[jj], bzv = bh[jj + HID], bnv = bh[jj + 2 * HID];
    float2 br2 = make_float2(brv, brv);
    float2 bz2 = make_float2(bzv, bzv);
    float2 bn2 = make_float2(bnv, bnv);

    if (active) hs[warp][0][j] = make_float2(0.0f, 0.0f);
    float2 h = make_float2(0.0f, 0.0f);
    __syncwarp();

    const float2* xgd = g_xg2 + (size_t)d * M_PAIRS * G3;
    const int t0 = (d == 0) ? 0 : (T_LEN - 1);
    const int dt = (d == 0) ? 1 : -1;

    float2 xr_n, xz_n, xn_n;
    {
        size_t row0 = ((size_t)t0 * BP + bp) * G3;
        xr_n = xgd[row0 + jj];
        xz_n = xgd[row0 + jj + HID];
        xn_n = xgd[row0 + jj + 2 * HID];
    }

    int par = 0;
    for (int s = 0; s < T_LEN; s++) {
        const int t = t0 + s * dt;
        float2 xr = xr_n, xz = xz_n, xn = xn_n;
        if (s + 1 < T_LEN) {
            size_t rown = ((size_t)(t + dt) * BP + bp) * G3;
            xr_n = xgd[rown + jj];
            xz_n = xgd[rown + jj + HID];
            xn_n = xgd[rown + jj + 2 * HID];
        }
        float2 ar = br2, az = bz2, an = bn2;
        const float2* hrow = hs[warp][par];
#pragma unroll
        for (int k = 0; k < HID; k++) {
            float2 hk = hrow[k];
            ar = ffma2(hk, wr2[k], ar);
            az = ffma2(hk, wz2[k], az);
            an = ffma2(hk, wn2[k], an);
        }
        // sigmoid(x) = 0.5 + 0.5*tanh(0.5x); HW tanh.approx
        float rX = fmaf(0.5f, tanhx(0.5f * (xr.x + ar.x)), 0.5f);
        float rY = fmaf(0.5f, tanhx(0.5f * (xr.y + ar.y)), 0.5f);
        float zX = fmaf(0.5f, tanhx(0.5f * (xz.x + az.x)), 0.5f);
        float zY = fmaf(0.5f, tanhx(0.5f * (xz.y + az.y)), 0.5f);
        float nX = tanhx(fmaf(rX, an.x, xn.x));
        float nY = tanhx(fmaf(rY, an.y, xn.y));
        h.x = fmaf(zX, h.x - nX, nX);
        h.y = fmaf(zY, h.y - nY, nY);

        if (active) hs[warp][par ^ 1][j] = h;
        __syncwarp();
        par ^= 1;
        if (active) seq2[((size_t)t * BP + bp) * D2 + d * HID + j] = h;
    }
}

// ---------------- FC epilogue on last timestep ----------------
__global__ void fc_kernel(const float* __restrict__ fc_w, const float* __restrict__ fc_b,
                          const float* __restrict__ omean, const float* __restrict__ ostd,
                          float* __restrict__ out) {
    int idx = blockIdx.x * blockDim.x + threadIdx.x;
    if (idx >= B_SZ * OUTD) return;
    int b = idx / OUTD, o = idx % OUTD;
    const float* lastp = (const float*)(g_sA2 + ((size_t)(T_LEN - 1) * BP + (b >> 1)) * D2);
    int par = b & 1;
    float acc = fc_b[o];
#pragma unroll
    for (int k = 0; k < D2; k++) acc += lastp[k * 2 + par] * fc_w[o * D2 + k];
    out[idx] = acc * ostd[o] + omean[o];
}

// ---------------- launch ----------------
static inline int xg_smem_bytes(int K) {
    int tile = K * 36 * 16 + K * XS_PAD * 8;   // wq + xs
    int st   = 64 * G3 * 8;                    // staging
    return (tile > st) ? tile : st;
}

extern "C" void kernel_launch(void* const* d_in, const int* in_sizes, int n_in,
                              void* d_out, int out_size) {
    const float* x         = (const float*)d_in[0];
    const float* fmean     = (const float*)d_in[1];
    const float* fstd      = (const float*)d_in[2];
    const float* omean     = (const float*)d_in[3];
    const float* ostd      = (const float*)d_in[4];
    const float* w_ih_l0   = (const float*)d_in[5];
    const float* w_hh_l0   = (const float*)d_in[6];
    const float* b_ih_l0   = (const float*)d_in[7];
    const float* b_hh_l0   = (const float*)d_in[8];
    const float* w_ih_rest = (const float*)d_in[9];
    const float* w_hh_rest = (const float*)d_in[10];
    const float* b_ih_rest = (const float*)d_in[11];
    const float* b_hh_rest = (const float*)d_in[12];
    const float* fc_w      = (const float*)d_in[13];
    const float* fc_b      = (const float*)d_in[14];
    float* out             = (float*)d_out;

    const int smem32 = xg_smem_bytes(FIN);
    const int smem46 = xg_smem_bytes(D2);
    cudaFuncSetAttribute(xg_kernel<FIN>, cudaFuncAttributeMaxDynamicSharedMemorySize, smem32);
    cudaFuncSetAttribute(xg_kernel<D2>,  cudaFuncAttributeMaxDynamicSharedMemorySize, smem46);

    dim3 xg_grid((unsigned)(M_PAIRS / 64), 2);
    dim3 gru_grid(BP / 2, 2);

    // layer 0: x (fused norm) -> sA2
    xg_kernel<FIN><<<xg_grid, 192, smem32>>>(0, w_ih_l0, b_ih_l0, x, fmean, fstd);
    gru_kernel<<<gru_grid, 64>>>(w_hh_l0, b_hh_l0, /*outsel=*/1);

    // layer 1: sA2 -> sB2
    xg_kernel<D2><<<xg_grid, 192, smem46>>>(1, w_ih_rest, b_ih_rest, nullptr, nullptr, nullptr);
    gru_kernel<<<gru_grid, 64>>>(w_hh_rest, b_hh_rest, /*outsel=*/2);

    // layer 2: sB2 -> sA2
    xg_kernel<D2><<<xg_grid, 192, smem46>>>(2, w_ih_rest + (size_t)2 * G3 * D2,
                                            b_ih_rest + 2 * G3, nullptr, nullptr, nullptr);
    gru_kernel<<<gru_grid, 64>>>(w_hh_rest + (size_t)2 * G3 * HID,
                                 b_hh_rest + 2 * G3, /*outsel=*/1);

    // FC epilogue
    {
        int threads = 256;
        int blocks = (B_SZ * OUTD + threads - 1) / threads;
        fc_kernel<<<blocks, threads>>>(fc_w, fc_b, omean, ostd, out);
    }
}

// round 10
// speedup vs baseline: 1.1617x; 1.0536x over previous
#include <cuda_runtime.h>
#include <cuda_fp16.h>
#include <cstdint>

#define T_LEN 512
#define B_SZ  2048
#define BP    1024                 // batch pairs
#define HID   23
#define G3    69                   // 3*H
#define FIN   32
#define D2    46                   // 2*H
#define OUTD  8
#define M_PAIRS ((size_t)T_LEN * BP)   // 524288 row-pairs

// ---------------- scratch (device globals; no allocation) ----------------
// pair-packed half2: .x = batch 2p, .y = batch 2p+1
__device__ __align__(16) __half2 g_xg2h[2 * M_PAIRS * G3];   // 290 MB
__device__ __align__(16) __half2 g_sA2h[M_PAIRS * D2];       // 96.5 MB
__device__ __align__(16) __half2 g_sB2h[M_PAIRS * D2];

__device__ __forceinline__ float2 ffma2(float2 a, float2 b, float2 c) {
    union U { float2 f; unsigned long long u; };
    U ua, ub, uc, ud;
    ua.f = a; ub.f = b; uc.f = c;
    asm("fma.rn.f32x2 %0, %1, %2, %3;"
        : "=l"(ud.u) : "l"(ua.u), "l"(ub.u), "l"(uc.u));
    return ud.f;
}

__device__ __forceinline__ float tanhx(float x) {
    float y;
    asm("tanh.approx.f32 %0, %1;" : "=f"(y) : "f"(x));
    return y;
}

// ---------------- input-gate GEMM (f32x2, half2 I/O) ------------------------
// Block: 192 thr = 6 warps. Warp w owns cols [12w,12w+12). 64 row-pairs/block;
// lane owns pairs {2*lane, 2*lane+1} -> one aligned LDS.128 per k.
// Weights: splat float4 (2 cols) -> broadcast LDS.128.
// insel==0 reads raw fp32 x with fused normalization.
#define XS_PAD 66   // even -> float4-aligned x rows

template <int K>
__global__ __launch_bounds__(192, 3)
void xg_kernel(int insel, const float* __restrict__ w_ih, const float* __restrict__ b_ih,
               const float* __restrict__ xin, const float* __restrict__ fmean,
               const float* __restrict__ fstd) {
    const int d = blockIdx.y;
    const float* W = w_ih + (size_t)d * G3 * K;

    extern __shared__ float sdyn[];
    float4* wq = (float4*)sdyn;                 // [K][36]
    float2* xs = (float2*)(wq + K * 36);        // [K][XS_PAD]

    const int tid  = threadIdx.x;
    const int w    = tid >> 5;
    const int lane = tid & 31;
    const size_t pbase = (size_t)blockIdx.x * 64;

    // weights -> smem (splat pairs)
    for (int idx = tid; idx < K * 36; idx += 192) {
        int k = idx / 36, t = idx % 36;
        int g0 = 2 * t, g1 = g0 + 1;
        float w0 = (g0 < G3) ? W[g0 * K + k] : 0.0f;
        float w1 = (g1 < G3) ? W[g1 * K + k] : 0.0f;
        wq[idx] = make_float4(w0, w0, w1, w1);
    }

    if (insel == 0) {
        // layer 0: raw x [B][T][FIN], fused normalization, transpose to k-major pairs
        __shared__ float fm_s[FIN], fi_s[FIN];
        if (tid < FIN) {
            float s = fstd[tid];
            float adj = (s == 0.0f) ? 1.0f : s;
            bool zero = (adj == 1.0f);
            fi_s[tid] = zero ? 0.0f : __fdividef(1.0f, adj);
            fm_s[tid] = zero ? 0.0f : fmean[tid];
        }
        __syncthreads();
        int t   = blockIdx.x >> 4;          // BP/64 = 16 blocks per timestep
        int bp0 = (blockIdx.x & 15) * 64;
        int b0  = 2 * bp0;
        for (int idx = tid; idx < 1024; idx += 192) {
            int row = idx >> 3;             // 0..127 (batch within tile)
            int q   = idx & 7;              // float4 within 32-feature row
            float4 v4 = *(const float4*)(xin + ((size_t)(b0 + row) * T_LEN + t) * FIN + q * 4);
            int p = row >> 1, comp = row & 1;
            int k0 = q * 4;
            const float* vv = &v4.x;
#pragma unroll
            for (int c = 0; c < 4; c++) {
                float val = (vv[c] - fm_s[k0 + c]) * fi_s[k0 + c];
                ((float*)&xs[(k0 + c) * XS_PAD + p])[comp] = val;
            }
        }
    } else {
        const __half2* in2 = (insel == 1) ? g_sA2h : g_sB2h;
        for (int idx = tid; idx < 64 * K; idx += 192) {
            int p = idx / K, k = idx % K;
            xs[k * XS_PAD + p] = __half22float2(in2[(pbase + p) * K + k]);
        }
    }

    // accumulators init with bias
    float2 acc0[12], acc1[12];
#pragma unroll
    for (int j = 0; j < 12; j++) {
        int c = w * 12 + j;
        float b = (c < G3) ? b_ih[d * G3 + c] : 0.0f;
        acc0[j] = make_float2(b, b);
        acc1[j] = make_float2(b, b);
    }
    __syncthreads();

#pragma unroll
    for (int k = 0; k < K; k++) {
        float4 xv = *(const float4*)&xs[k * XS_PAD + 2 * lane];   // pairs 2l, 2l+1
        float2 xa = make_float2(xv.x, xv.y);
        float2 xb = make_float2(xv.z, xv.w);
        const float4* wr = wq + k * 36 + w * 6;
#pragma unroll
        for (int t6 = 0; t6 < 6; t6++) {
            float4 q = wr[t6];
            float2 w0 = make_float2(q.x, q.y);
            float2 w1 = make_float2(q.z, q.w);
            acc0[2 * t6]     = ffma2(xa, w0, acc0[2 * t6]);
            acc0[2 * t6 + 1] = ffma2(xa, w1, acc0[2 * t6 + 1]);
            acc1[2 * t6]     = ffma2(xb, w0, acc1[2 * t6]);
            acc1[2 * t6 + 1] = ffma2(xb, w1, acc1[2 * t6 + 1]);
        }
    }

    // stage (half2) + contiguous 16B copy-out
    __syncthreads();
    __half2* st = (__half2*)sdyn;   // [64][69]
#pragma unroll
    for (int j = 0; j < 12; j++) {
        int c = w * 12 + j;
        if (c < G3) {
            st[(size_t)(2 * lane) * G3 + c]     = __float22half2_rn(acc0[j]);
            st[(size_t)(2 * lane + 1) * G3 + c] = __float22half2_rn(acc1[j]);
        }
    }
    __syncthreads();

    uint4* dst = (uint4*)(g_xg2h + (size_t)d * M_PAIRS * G3 + pbase * G3);
    const uint4* src = (const uint4*)st;
    const int n16 = 64 * G3 * 4 / 16;   // 1104
    for (int i = tid; i < n16; i += 192) dst[i] = src[i];
}

// ---------------- GRU recurrence (f32x2): one warp per (batch pair, dir) ----------------
__global__ __launch_bounds__(64)
void gru_kernel(const float* __restrict__ w_hh, const float* __restrict__ b_hh, int outsel) {
    const int d = blockIdx.y;
    const int warp = threadIdx.x >> 5;
    const int lane = threadIdx.x & 31;
    const int bp = blockIdx.x * 2 + warp;
    __half2* seq2 = (outsel == 1) ? g_sA2h : g_sB2h;

    __shared__ float2 hs[2][2][HID + 1];   // [warp][parity][unit]

    const float* W  = w_hh + (size_t)d * G3 * HID;
    const float* bh = b_hh + d * G3;

    const int j = lane;
    const bool active = (j < HID);
    const int jj = active ? j : 0;

    float2 wr2[HID], wz2[HID], wn2[HID];
#pragma unroll
    for (int k = 0; k < HID; k++) {
        float wr = W[(jj) * HID + k];
        float wz = W[(jj + HID) * HID + k];
        float wn = W[(jj + 2 * HID) * HID + k];
        wr2[k] = make_float2(wr, wr);
        wz2[k] = make_float2(wz, wz);
        wn2[k] = make_float2(wn, wn);
    }
    float brv = bh[jj], bzv = bh[jj + HID], bnv = bh[jj + 2 * HID];
    float2 br2 = make_float2(brv, brv);
    float2 bz2 = make_float2(bzv, bzv);
    float2 bn2 = make_float2(bnv, bnv);

    if (active) hs[warp][0][j] = make_float2(0.0f, 0.0f);
    float2 h = make_float2(0.0f, 0.0f);
    __syncwarp();

    const __half2* xgd = g_xg2h + (size_t)d * M_PAIRS * G3;
    const int t0 = (d == 0) ? 0 : (T_LEN - 1);
    const int dt = (d == 0) ? 1 : -1;

    __half2 xr_n, xz_n, xn_n;
    {
        size_t row0 = ((size_t)t0 * BP + bp) * G3;
        xr_n = xgd[row0 + jj];
        xz_n = xgd[row0 + jj + HID];
        xn_n = xgd[row0 + jj + 2 * HID];
    }

    int par = 0;
    for (int s = 0; s < T_LEN; s++) {
        const int t = t0 + s * dt;
        float2 xr = __half22float2(xr_n);
        float2 xz = __half22float2(xz_n);
        float2 xn = __half22float2(xn_n);
        if (s + 1 < T_LEN) {
            size_t rown = ((size_t)(t + dt) * BP + bp) * G3;
            xr_n = xgd[rown + jj];
            xz_n = xgd[rown + jj + HID];
            xn_n = xgd[rown + jj + 2 * HID];
        }
        float2 ar = br2, az = bz2, an = bn2;
        const float2* hrow = hs[warp][par];
#pragma unroll
        for (int k = 0; k < HID; k++) {
            float2 hk = hrow[k];
            ar = ffma2(hk, wr2[k], ar);
            az = ffma2(hk, wz2[k], az);
            an = ffma2(hk, wn2[k], an);
        }
        // sigmoid(x) = 0.5 + 0.5*tanh(0.5x); HW tanh.approx
        float rX = fmaf(0.5f, tanhx(0.5f * (xr.x + ar.x)), 0.5f);
        float rY = fmaf(0.5f, tanhx(0.5f * (xr.y + ar.y)), 0.5f);
        float zX = fmaf(0.5f, tanhx(0.5f * (xz.x + az.x)), 0.5f);
        float zY = fmaf(0.5f, tanhx(0.5f * (xz.y + az.y)), 0.5f);
        float nX = tanhx(fmaf(rX, an.x, xn.x));
        float nY = tanhx(fmaf(rY, an.y, xn.y));
        h.x = fmaf(zX, h.x - nX, nX);
        h.y = fmaf(zY, h.y - nY, nY);

        if (active) hs[warp][par ^ 1][j] = h;
        __syncwarp();
        par ^= 1;
        if (active) seq2[((size_t)t * BP + bp) * D2 + d * HID + j] = __float22half2_rn(h);
    }
}

// ---------------- FC epilogue on last timestep ----------------
__global__ void fc_kernel(const float* __restrict__ fc_w, const float* __restrict__ fc_b,
                          const float* __restrict__ omean, const float* __restrict__ ostd,
                          float* __restrict__ out) {
    int idx = blockIdx.x * blockDim.x + threadIdx.x;
    if (idx >= B_SZ * OUTD) return;
    int b = idx / OUTD, o = idx % OUTD;
    const __half2* lastp = g_sA2h + ((size_t)(T_LEN - 1) * BP + (b >> 1)) * D2;
    int par = b & 1;
    float acc = fc_b[o];
#pragma unroll
    for (int k = 0; k < D2; k++) {
        float2 v = __half22float2(lastp[k]);
        float hv = par ? v.y : v.x;
        acc += hv * fc_w[o * D2 + k];
    }
    out[idx] = acc * ostd[o] + omean[o];
}

// ---------------- launch ----------------
static inline int xg_smem_bytes(int K) {
    int tile = K * 36 * 16 + K * XS_PAD * 8;   // wq + xs
    int st   = 64 * G3 * 4;                    // half2 staging
    return (tile > st) ? tile : st;
}

extern "C" void kernel_launch(void* const* d_in, const int* in_sizes, int n_in,
                              void* d_out, int out_size) {
    const float* x         = (const float*)d_in[0];
    const float* fmean     = (const float*)d_in[1];
    const float* fstd      = (const float*)d_in[2];
    const float* omean     = (const float*)d_in[3];
    const float* ostd      = (const float*)d_in[4];
    const float* w_ih_l0   = (const float*)d_in[5];
    const float* w_hh_l0   = (const float*)d_in[6];
    const float* b_ih_l0   = (const float*)d_in[7];
    const float* b_hh_l0   = (const float*)d_in[8];
    const float* w_ih_rest = (const float*)d_in[9];
    const float* w_hh_rest = (const float*)d_in[10];
    const float* b_ih_rest = (const float*)d_in[11];
    const float* b_hh_rest = (const float*)d_in[12];
    const float* fc_w      = (const float*)d_in[13];
    const float* fc_b      = (const float*)d_in[14];
    float* out             = (float*)d_out;

    const int smem32 = xg_smem_bytes(FIN);
    const int smem46 = xg_smem_bytes(D2);
    cudaFuncSetAttribute(xg_kernel<FIN>, cudaFuncAttributeMaxDynamicSharedMemorySize, smem32);
    cudaFuncSetAttribute(xg_kernel<D2>,  cudaFuncAttributeMaxDynamicSharedMemorySize, smem46);

    dim3 xg_grid((unsigned)(M_PAIRS / 64), 2);
    dim3 gru_grid(BP / 2, 2);

    // layer 0: x (fused norm) -> sA2
    xg_kernel<FIN><<<xg_grid, 192, smem32>>>(0, w_ih_l0, b_ih_l0, x, fmean, fstd);
    gru_kernel<<<gru_grid, 64>>>(w_hh_l0, b_hh_l0, /*outsel=*/1);

    // layer 1: sA2 -> sB2
    xg_kernel<D2><<<xg_grid, 192, smem46>>>(1, w_ih_rest, b_ih_rest, nullptr, nullptr, nullptr);
    gru_kernel<<<gru_grid, 64>>>(w_hh_rest, b_hh_rest, /*outsel=*/2);

    // layer 2: sB2 -> sA2
    xg_kernel<D2><<<xg_grid, 192, smem46>>>(2, w_ih_rest + (size_t)2 * G3 * D2,
                                            b_ih_rest + 2 * G3, nullptr, nullptr, nullptr);
    gru_kernel<<<gru_grid, 64>>>(w_hh_rest + (size_t)2 * G3 * HID,
                                 b_hh_rest + 2 * G3, /*outsel=*/1);

    // FC epilogue
    {
        int threads = 256;
        int blocks = (B_SZ * OUTD + threads - 1) / threads;
        fc_kernel<<<blocks, threads>>>(fc_w, fc_b, omean, ostd, out);
    }
}